// round 13
// baseline (speedup 1.0000x reference)
#include <cuda_runtime.h>
#include <cuda_bf16.h>
#include <cstdint>

#define N_NODES   20000
#define N_INPUT   64
#define KMAX      12
#define NBITS     64
#define N_OUT     10
#define NBATCH    64
#define TSTEPS    128
#define LUTW      128         /* 4096 bits / 32 words */
#define DUMMY     20000
#define ST_SZ     20008
#define TPB_MAIN  1024
#define NPC       68          /* nodes per CTA (even) */
#define PAIRS     (NPC / 2)   /* 34 */
#define GRID_MAIN 294         /* 294*68 = 19992 >= 19936 ; 2 CTAs/SM */
#define SLUT_WORDS (NPC * LUTW)          /* 8704 words */
#define SLUT_BYTES (SLUT_WORDS * 4)      /* 34816 bytes -> 2 CTAs/SM */

// LUT bit layout (remapped for vectorized packing):
//   entry e -> word ((e>>7)<<2) | (e&3),  bit (e>>2)&31

// ---------------- device globals (scratch; no allocations allowed) ----------------
__device__ __align__(16) unsigned short g_adj[N_NODES * 16];   // lane-reversed packed adjacency
__device__ __align__(16) unsigned int g_lut[N_NODES * LUTW];   // 10.24 MB bit-packed LUT (remapped layout)
__device__ unsigned char g_non[N_NODES];                       // no-neighbor flag per node
__device__ uint2         g_st[2][ST_SZ];                       // bit-packed states; slot 20000 = always-0 dummy
__device__ uint2         g_u[TSTEPS * 64];                     // input-layer bits u[t][j]
__device__ uint2         g_xb[NBATCH * TSTEPS];                // packed x bits [b][t]
__device__ uint2         g_wc[64];                             // packed w_in columns
__device__ unsigned int  g_warr[32 * 32];                      // 32 per-warp-slot arrival counters, 128B apart

// ---------------- preprocessing (fused: 3 kernels) ----------------

// pre1: pack_x (blocks 0..1023) + pack_w (blocks 1024..1031)
__global__ void k_pre1(const int* __restrict__ x, const int* __restrict__ w_in) {
    int lane = threadIdx.x & 31;
    if (blockIdx.x < 1024) {
        int wid = (blockIdx.x * 256 + threadIdx.x) >> 5;   // 0..8191
        int b = wid >> 7, t = wid & 127;
        const int* p = x + ((size_t)b * TSTEPS + t) * NBITS;
        unsigned lo = __ballot_sync(0xffffffffu, p[lane] != 0);
        unsigned hi = __ballot_sync(0xffffffffu, p[lane + 32] != 0);
        if (lane == 0) g_xb[b * TSTEPS + t] = make_uint2(lo, hi);
    } else {
        int wid = ((blockIdx.x - 1024) * 256 + threadIdx.x) >> 5;  // 0..63
        unsigned lo = __ballot_sync(0xffffffffu, w_in[lane * 64 + wid] != 0);
        unsigned hi = __ballot_sync(0xffffffffu, w_in[(lane + 32) * 64 + wid] != 0);
        if (lane == 0) g_wc[wid] = make_uint2(lo, hi);
    }
}

// pre2: build_u (blocks 0..1023) + pack_adj (blocks 1024..1102)
__global__ void k_pre2(const int* __restrict__ adj_list, const int* __restrict__ adj_mask) {
    int lane = threadIdx.x & 31;
    if (blockIdx.x < 1024) {
        int wid = (blockIdx.x * 256 + threadIdx.x) >> 5;   // 0..8191
        int t = wid >> 6, j = wid & 63;
        uint2 wc = g_wc[j];
        uint2 xa = g_xb[lane * TSTEPS + t];
        uint2 xb = g_xb[(lane + 32) * TSTEPS + t];
        unsigned lo = __ballot_sync(0xffffffffu, ((xa.x & wc.x) | (xa.y & wc.y)) != 0);
        unsigned hi = __ballot_sync(0xffffffffu, ((xb.x & wc.x) | (xb.y & wc.y)) != 0);
        if (lane == 0) g_u[t * 64 + j] = make_uint2(lo, hi);
    } else {
        int n = (blockIdx.x - 1024) * 256 + threadIdx.x;
        if (n >= N_NODES) return;
        unsigned a[12];
        int any = 0;
#pragma unroll
        for (int k = 0; k < KMAX; k++) {
            int m = adj_mask[n * KMAX + k];
            any |= m;
            a[k] = m ? (unsigned)adj_list[n * KMAX + k] : (unsigned)DUMMY;
        }
        if (!any) {
#pragma unroll
            for (int k = 0; k < KMAX; k++) a[k] = DUMMY;
            a[11] = (unsigned)n;   // idx = old state bit (identity LUT)
        }
        g_non[n] = (unsigned char)(!any);
        unsigned r[16];
#pragma unroll
        for (int l = 0; l < 12; l++) r[l] = a[11 - l];     // lane-reversed
        r[12] = r[13] = r[14] = r[15] = DUMMY;
        uint4 v0, v1;
        v0.x = r[0]  | (r[1]  << 16); v0.y = r[2]  | (r[3]  << 16);
        v0.z = r[4]  | (r[5]  << 16); v0.w = r[6]  | (r[7]  << 16);
        v1.x = r[8]  | (r[9]  << 16); v1.y = r[10] | (r[11] << 16);
        v1.z = r[12] | (r[13] << 16); v1.w = r[14] | (r[15] << 16);
        ((uint4*)g_adj)[n * 2]     = v0;
        ((uint4*)g_adj)[n * 2 + 1] = v1;
    }
}

// pre3: pack_lut vectorized (blocks 0..79999) + state/barrier init (80000..80078).
__global__ void k_pre3(const int* __restrict__ lut, const int* __restrict__ init_states) {
    if (blockIdx.x < 80000) {
        int gw   = blockIdx.x * 8 + (threadIdx.x >> 5);    // 0..639999
        int lane = threadIdx.x & 31;
        int node = gw >> 5, chunk = gw & 31;
        uint4 wout;
        if (g_non[node]) {
            wout = make_uint4(0u, (chunk == 0) ? 1u : 0u, 0u, 0u);
        } else {
            const int4* p = (const int4*)(lut + (size_t)node * 4096 + (size_t)chunk * 128);
            int4 v = p[lane];
            wout.x = __ballot_sync(0xffffffffu, v.x != 0);
            wout.y = __ballot_sync(0xffffffffu, v.y != 0);
            wout.z = __ballot_sync(0xffffffffu, v.z != 0);
            wout.w = __ballot_sync(0xffffffffu, v.w != 0);
        }
        if (lane == 0)
            ((uint4*)g_lut)[node * (LUTW / 4) + chunk] = wout;
    } else {
        int i = (blockIdx.x - 80000) * 256 + threadIdx.x;
        if (i < 32 * 32) g_warr[i] = 0;
        if (i >= ST_SZ) return;
        if (i < N_INPUT) {
            g_st[0][i] = g_u[i];                           // u[0][i]
        } else if (i < N_NODES) {
            int s = init_states[i];
            g_st[0][i] = s ? make_uint2(0xffffffffu, 0xffffffffu) : make_uint2(0u, 0u);
        } else {                                            // dummy + pad: zero both buffers
            g_st[0][i] = make_uint2(0u, 0u);
            g_st[1][i] = make_uint2(0u, 0u);
        }
    }
}

// ---------------- main persistent kernel ----------------

// 32x32 bit-matrix transpose distributed across a warp (5 butterfly stages).
// Stages 16 and 8 are pure byte permutations -> single PRMT each.
__device__ __forceinline__ unsigned btrans32(unsigned x, int lane,
                                             unsigned sel16, unsigned sel8) {
    unsigned y;
    y = __shfl_xor_sync(0xffffffffu, x, 16);
    x = __byte_perm(x, y, sel16);                          // stage 16: PRMT
    y = __shfl_xor_sync(0xffffffffu, x, 8);
    x = __byte_perm(x, y, sel8);                           // stage 8: PRMT
    y = __shfl_xor_sync(0xffffffffu, x, 4);
    x = (lane & 4)  ? ((x & 0xf0f0f0f0u) | ((y & 0xf0f0f0f0u) >> 4))
                    : ((x & 0x0f0f0f0fu) | ((y & 0x0f0f0f0fu) << 4));
    y = __shfl_xor_sync(0xffffffffu, x, 2);
    x = (lane & 2)  ? ((x & 0xccccccccu) | ((y & 0xccccccccu) >> 2))
                    : ((x & 0x33333333u) | ((y & 0x33333333u) << 2));
    y = __shfl_xor_sync(0xffffffffu, x, 1);
    x = (lane & 1)  ? ((x & 0xaaaaaaaau) | ((y & 0xaaaaaaaau) >> 1))
                    : ((x & 0x55555555u) | ((y & 0x55555555u) << 1));
    return x;
}

// remapped-layout LUT lookup: entry idx -> word ((idx>>7)<<2)|(idx&3), bit (idx>>2)&31
__device__ __forceinline__ unsigned lut_bit(const unsigned* __restrict__ row, unsigned idx) {
    unsigned wofs = ((idx >> 5) & ~3u) | (idx & 3u);
    return (row[wofs] >> ((idx >> 2) & 31u)) & 1u;
}

__device__ __forceinline__ unsigned ld_acq(const unsigned* p) {
    unsigned v;
    asm volatile("ld.acquire.gpu.global.u32 %0, [%1];" : "=r"(v) : "l"(p) : "memory");
    return v;
}

__global__ void __launch_bounds__(TPB_MAIN, 2) k_main() {
    extern __shared__ unsigned s_lut[];                    // NPC * 128 words (34 KB)
    const int lane = threadIdx.x & 31;
    const int w    = threadIdx.x >> 5;                     // warp id in CTA (0..31)
    const int nb   = gridDim.x;
    const int bid  = blockIdx.x;
    const int start = N_INPUT + bid * NPC;                 // first node owned by this CTA
    const unsigned sel16 = (lane & 16) ? 0x3276u : 0x5410u;
    const unsigned sel8  = (lane & 8)  ? 0x3715u : 0x6240u;

    // stage this CTA's LUT slice into shared memory (one-time)
    for (int i = threadIdx.x; i < SLUT_WORDS; i += TPB_MAIN) {
        int node = start + (i >> 7);
        s_lut[i] = (node < N_NODES) ? g_lut[node * LUTW + (i & 127)] : 0u;
    }

    // Pairing: warp w owns pair w; warps 30,31 additionally own pairs 32,33
    // (= w+2), keeping double duty OFF the polling warp (0) and staging warps.
    // Lanes 0..11 hold A's lane-reversed adjacency, lanes 16..27 hold B's.
    const bool laneA = (lane < KMAX);
    const bool laneB = (lane >= 16) && (lane < 16 + KMAX);
    const bool gath  = laneA || laneB;
    const int  niters = (w >= 30) ? 2 : 1;                 // pairs: w, and w+2 for w>=30

    unsigned adjreg[2];
#pragma unroll
    for (int i = 0; i < 2; i++) {
        int p = (i == 0) ? w : (w + 2);
        unsigned ai = DUMMY;
        if (i == 0 || w >= 30) {
            int nA = start + 2 * p, nB = nA + 1;
            if (laneA && nA < N_NODES) ai = (unsigned)g_adj[nA * 16 + lane];
            if (laneB && nB < N_NODES) ai = (unsigned)g_adj[nB * 16 + (lane - 16)];
        }
        adjreg[i] = ai;
    }
    __syncthreads();                                       // s_lut ready

    int cur = 0;
    for (int t = 0; t < TSTEPS; t++) {
        const uint2* __restrict__ S = g_st[cur];
        uint2* __restrict__ D = g_st[cur ^ 1];

        // CTA 0 stages next step's input-layer bits into the destination buffer
        if (bid == 0 && threadIdx.x < 64 && t + 1 < TSTEPS)
            D[threadIdx.x] = g_u[(t + 1) * 64 + threadIdx.x];

        // prefetch this warp's gathers before any compute (hide L2 latency)
        uint2 wv[2];
        wv[0] = wv[1] = make_uint2(0u, 0u);
        if (gath) {
            wv[0] = __ldcg(&S[adjreg[0]]);
            if (niters == 2) wv[1] = __ldcg(&S[adjreg[1]]);
        }

#pragma unroll
        for (int i = 0; i < 2; i++) {
            if (i >= niters) break;
            int p  = (i == 0) ? w : (w + 2);
            int nA = start + 2 * p;
            unsigned tl = btrans32(wv[i].x, lane, sel16, sel8);  // [idxA|idxB<<16] b0-31
            unsigned th = btrans32(wv[i].y, lane, sel16, sel8);  // b32-63
            unsigned iAL = tl & 0xfffu, iBL = (tl >> 16) & 0xfffu;
            unsigned iAH = th & 0xfffu, iBH = (th >> 16) & 0xfffu;
            const unsigned* rowA = s_lut + (p << 8);        // local node 2p
            const unsigned* rowB = rowA + LUTW;             // local node 2p+1
            unsigned bAL = lut_bit(rowA, iAL);
            unsigned bAH = lut_bit(rowA, iAH);
            unsigned bBL = lut_bit(rowB, iBL);
            unsigned bBH = lut_bit(rowB, iBH);
            unsigned mAL = __ballot_sync(0xffffffffu, bAL);
            unsigned mAH = __ballot_sync(0xffffffffu, bAH);
            unsigned mBL = __ballot_sync(0xffffffffu, bBL);
            unsigned mBH = __ballot_sync(0xffffffffu, bBH);
            // nA even & N_NODES even -> nA valid implies nB valid; single STG.128.
            if (lane == 0 && nA < N_NODES)
                *(uint4*)&D[nA] = make_uint4(mAL, mAH, mBL, mBH);
        }

        // ---- distributed barrier ----
        // Per-warp arrive: syncwarp makes warp-mates' stores (CTA0 staging)
        // hb-before lane 0's release-RED on this warp-slot's counter.
        __syncwarp();
        if (lane == 0)
            asm volatile("red.release.gpu.global.add.u32 [%0], %1;"
                         :: "l"(&g_warr[w * 32]), "r"(1u) : "memory");
        // Detection: warp 0's lane j acquire-polls counter j (32 lines, parallel);
        // acquire on counter j syncs-with every CTA's warp-j release.
        if (w == 0) {
            const unsigned target = (unsigned)nb * (unsigned)(t + 1);
            unsigned v;
            do {
                v = ld_acq(&g_warr[lane * 32]);
            } while (!__all_sync(0xffffffffu, v >= target));
        }
        __syncthreads();                                    // propagate hb to whole CTA
        cur ^= 1;
    }
}

// ---------------- readout: sigmoid(states[:,64:] @ W^T + b) ----------------

__global__ void k_readout(const float* __restrict__ W, const float* __restrict__ bias,
                          float* __restrict__ out) {
    int b   = blockIdx.x;        // 64 blocks
    int tid = threadIdx.x;       // 256 threads
    int lane = tid & 31, wrp = tid >> 5;
    const uint2* __restrict__ S = g_st[0];   // TSTEPS even -> final states in buffer 0

    float acc[N_OUT];
#pragma unroll
    for (int o = 0; o < N_OUT; o++) acc[o] = 0.f;

    const int bsh = b & 31;
    for (int n = N_INPUT + tid; n < N_NODES; n += blockDim.x) {
        uint2 w = S[n];
        unsigned word = (b < 32) ? w.x : w.y;
        float bit = (float)((word >> bsh) & 1u);
        const float* wp = W + (n - N_INPUT);
#pragma unroll
        for (int o = 0; o < N_OUT; o++)
            acc[o] += bit * wp[o * (N_NODES - N_INPUT)];
    }

    __shared__ float part[8][N_OUT];
#pragma unroll
    for (int o = 0; o < N_OUT; o++) {
        float v = acc[o];
#pragma unroll
        for (int off = 16; off; off >>= 1) v += __shfl_down_sync(0xffffffffu, v, off);
        if (lane == 0) part[wrp][o] = v;
    }
    __syncthreads();
    if (tid < N_OUT) {
        float s = bias[tid];
#pragma unroll
        for (int w2 = 0; w2 < 8; w2++) s += part[w2][tid];
        out[b * N_OUT + tid] = 1.0f / (1.0f + expf(-s));
    }
}

// ---------------- launch ----------------

extern "C" void kernel_launch(void* const* d_in, const int* in_sizes, int n_in,
                              void* d_out, int out_size) {
    (void)in_sizes; (void)n_in; (void)out_size;
    const int*   x           = (const int*)d_in[0];
    const int*   w_in        = (const int*)d_in[1];
    const int*   adj_list    = (const int*)d_in[2];
    const int*   adj_mask    = (const int*)d_in[3];
    const int*   lut         = (const int*)d_in[4];
    const int*   init_states = (const int*)d_in[5];
    const float* W_out       = (const float*)d_in[6];
    const float* b_out       = (const float*)d_in[7];
    float* out = (float*)d_out;

    k_pre1<<<1032, 256>>>(x, w_in);                        // pack_x + pack_w
    k_pre2<<<1103, 256>>>(adj_list, adj_mask);             // build_u + pack_adj
    k_pre3<<<80079, 256>>>(lut, init_states);              // pack_lut (vec) + init

    cudaFuncSetAttribute(k_main, cudaFuncAttributeMaxDynamicSharedMemorySize, SLUT_BYTES);
    k_main<<<GRID_MAIN, TPB_MAIN, SLUT_BYTES>>>();         // 4th launch -> ncu capture
    k_readout<<<NBATCH, 256>>>(W_out, b_out, out);
}

// round 14
// speedup vs baseline: 1.3163x; 1.3163x over previous
#include <cuda_runtime.h>
#include <cuda_bf16.h>
#include <cstdint>

#define N_NODES   20000
#define N_INPUT   64
#define KMAX      12
#define NBITS     64
#define N_OUT     10
#define NBATCH    64
#define TSTEPS    128
#define LUTW      128         /* 4096 bits / 32 words */
#define DUMMY     20000
#define ST_SZ     20008
#define TPB_MAIN  1024
#define NPC       68          /* nodes per CTA (even) */
#define PAIRS     (NPC / 2)   /* 34 */
#define GRID_MAIN 294         /* 294*68 = 19992 >= 19936 ; 2 CTAs/SM */
#define SLUT_WORDS (NPC * LUTW)          /* 8704 words */
#define SLUT_BYTES (SLUT_WORDS * 4)      /* 34816 bytes -> 2 CTAs/SM */

// LUT bit layout (remapped for vectorized packing):
//   entry e -> word ((e>>7)<<2) | (e&3),  bit (e>>2)&31

// ---------------- device globals (scratch; no allocations allowed) ----------------
__device__ __align__(16) unsigned short g_adj[N_NODES * 16];   // lane-reversed packed adjacency
__device__ __align__(16) unsigned int g_lut[N_NODES * LUTW];   // 10.24 MB bit-packed LUT (remapped layout)
__device__ unsigned char g_non[N_NODES];                       // no-neighbor flag per node
__device__ uint2         g_st[2][ST_SZ];                       // bit-packed states; slot 20000 = always-0 dummy
__device__ uint2         g_u[TSTEPS * 64];                     // input-layer bits u[t][j]
__device__ uint2         g_xb[NBATCH * TSTEPS];                // packed x bits [b][t]
__device__ uint2         g_wc[64];                             // packed w_in columns
__device__ unsigned int  g_arrive;                             // MONOTONIC arrival counter (REDG target)

// ---------------- preprocessing (fused: 3 kernels) ----------------

// pre1: pack_x (blocks 0..1023) + pack_w (blocks 1024..1031)
__global__ void k_pre1(const int* __restrict__ x, const int* __restrict__ w_in) {
    int lane = threadIdx.x & 31;
    if (blockIdx.x < 1024) {
        int wid = (blockIdx.x * 256 + threadIdx.x) >> 5;   // 0..8191
        int b = wid >> 7, t = wid & 127;
        const int* p = x + ((size_t)b * TSTEPS + t) * NBITS;
        unsigned lo = __ballot_sync(0xffffffffu, p[lane] != 0);
        unsigned hi = __ballot_sync(0xffffffffu, p[lane + 32] != 0);
        if (lane == 0) g_xb[b * TSTEPS + t] = make_uint2(lo, hi);
    } else {
        int wid = ((blockIdx.x - 1024) * 256 + threadIdx.x) >> 5;  // 0..63
        unsigned lo = __ballot_sync(0xffffffffu, w_in[lane * 64 + wid] != 0);
        unsigned hi = __ballot_sync(0xffffffffu, w_in[(lane + 32) * 64 + wid] != 0);
        if (lane == 0) g_wc[wid] = make_uint2(lo, hi);
    }
}

// pre2: build_u (blocks 0..1023) + pack_adj (blocks 1024..1102)
__global__ void k_pre2(const int* __restrict__ adj_list, const int* __restrict__ adj_mask) {
    int lane = threadIdx.x & 31;
    if (blockIdx.x < 1024) {
        int wid = (blockIdx.x * 256 + threadIdx.x) >> 5;   // 0..8191
        int t = wid >> 6, j = wid & 63;
        uint2 wc = g_wc[j];
        uint2 xa = g_xb[lane * TSTEPS + t];
        uint2 xb = g_xb[(lane + 32) * TSTEPS + t];
        unsigned lo = __ballot_sync(0xffffffffu, ((xa.x & wc.x) | (xa.y & wc.y)) != 0);
        unsigned hi = __ballot_sync(0xffffffffu, ((xb.x & wc.x) | (xb.y & wc.y)) != 0);
        if (lane == 0) g_u[t * 64 + j] = make_uint2(lo, hi);
    } else {
        int n = (blockIdx.x - 1024) * 256 + threadIdx.x;
        if (n >= N_NODES) return;
        unsigned a[12];
        int any = 0;
#pragma unroll
        for (int k = 0; k < KMAX; k++) {
            int m = adj_mask[n * KMAX + k];
            any |= m;
            a[k] = m ? (unsigned)adj_list[n * KMAX + k] : (unsigned)DUMMY;
        }
        if (!any) {
#pragma unroll
            for (int k = 0; k < KMAX; k++) a[k] = DUMMY;
            a[11] = (unsigned)n;   // idx = old state bit (identity LUT)
        }
        g_non[n] = (unsigned char)(!any);
        unsigned r[16];
#pragma unroll
        for (int l = 0; l < 12; l++) r[l] = a[11 - l];     // lane-reversed
        r[12] = r[13] = r[14] = r[15] = DUMMY;
        uint4 v0, v1;
        v0.x = r[0]  | (r[1]  << 16); v0.y = r[2]  | (r[3]  << 16);
        v0.z = r[4]  | (r[5]  << 16); v0.w = r[6]  | (r[7]  << 16);
        v1.x = r[8]  | (r[9]  << 16); v1.y = r[10] | (r[11] << 16);
        v1.z = r[12] | (r[13] << 16); v1.w = r[14] | (r[15] << 16);
        ((uint4*)g_adj)[n * 2]     = v0;
        ((uint4*)g_adj)[n * 2 + 1] = v1;
    }
}

// pre3: pack_lut vectorized (blocks 0..79999) + state/barrier init (80000..80078).
__global__ void k_pre3(const int* __restrict__ lut, const int* __restrict__ init_states) {
    if (blockIdx.x < 80000) {
        int gw   = blockIdx.x * 8 + (threadIdx.x >> 5);    // 0..639999
        int lane = threadIdx.x & 31;
        int node = gw >> 5, chunk = gw & 31;
        uint4 wout;
        if (g_non[node]) {
            wout = make_uint4(0u, (chunk == 0) ? 1u : 0u, 0u, 0u);
        } else {
            const int4* p = (const int4*)(lut + (size_t)node * 4096 + (size_t)chunk * 128);
            int4 v = __ldcs(&p[lane]);                     // streaming: don't thrash L2
            wout.x = __ballot_sync(0xffffffffu, v.x != 0);
            wout.y = __ballot_sync(0xffffffffu, v.y != 0);
            wout.z = __ballot_sync(0xffffffffu, v.z != 0);
            wout.w = __ballot_sync(0xffffffffu, v.w != 0);
        }
        if (lane == 0)
            ((uint4*)g_lut)[node * (LUTW / 4) + chunk] = wout;
    } else {
        int i = (blockIdx.x - 80000) * 256 + threadIdx.x;
        if (i == 0) g_arrive = 0;
        if (i >= ST_SZ) return;
        if (i < N_INPUT) {
            g_st[0][i] = g_u[i];                           // u[0][i]
        } else if (i < N_NODES) {
            int s = init_states[i];
            g_st[0][i] = s ? make_uint2(0xffffffffu, 0xffffffffu) : make_uint2(0u, 0u);
        } else {                                            // dummy + pad: zero both buffers
            g_st[0][i] = make_uint2(0u, 0u);
            g_st[1][i] = make_uint2(0u, 0u);
        }
    }
}

// ---------------- main persistent kernel ----------------

// 32x32 bit-matrix transpose distributed across a warp (5 butterfly stages).
// Stages 16 and 8 are pure byte permutations -> single PRMT each.
__device__ __forceinline__ unsigned btrans32(unsigned x, int lane,
                                             unsigned sel16, unsigned sel8) {
    unsigned y;
    y = __shfl_xor_sync(0xffffffffu, x, 16);
    x = __byte_perm(x, y, sel16);                          // stage 16: PRMT
    y = __shfl_xor_sync(0xffffffffu, x, 8);
    x = __byte_perm(x, y, sel8);                           // stage 8: PRMT
    y = __shfl_xor_sync(0xffffffffu, x, 4);
    x = (lane & 4)  ? ((x & 0xf0f0f0f0u) | ((y & 0xf0f0f0f0u) >> 4))
                    : ((x & 0x0f0f0f0fu) | ((y & 0x0f0f0f0fu) << 4));
    y = __shfl_xor_sync(0xffffffffu, x, 2);
    x = (lane & 2)  ? ((x & 0xccccccccu) | ((y & 0xccccccccu) >> 2))
                    : ((x & 0x33333333u) | ((y & 0x33333333u) << 2));
    y = __shfl_xor_sync(0xffffffffu, x, 1);
    x = (lane & 1)  ? ((x & 0xaaaaaaaau) | ((y & 0xaaaaaaaau) >> 1))
                    : ((x & 0x55555555u) | ((y & 0x55555555u) << 1));
    return x;
}

// remapped-layout LUT lookup: entry idx -> word ((idx>>7)<<2)|(idx&3), bit (idx>>2)&31
__device__ __forceinline__ unsigned lut_bit(const unsigned* __restrict__ row, unsigned idx) {
    unsigned wofs = ((idx >> 5) & ~3u) | (idx & 3u);
    return (row[wofs] >> ((idx >> 2) & 31u)) & 1u;
}

// Validated fence-free barrier (R11/R12): REDG release arrive + acquire spin on
// the single monotonic counter (single hop). No MEMBAR.GL, no CCTL.IVALL.
__device__ __forceinline__ void grid_bar(int t, int nblocks) {
    __syncthreads();
    if (threadIdx.x == 0) {
        asm volatile("red.release.gpu.global.add.u32 [%0], %1;"
                     :: "l"(&g_arrive), "r"(1u) : "memory");
        const unsigned target = (unsigned)nblocks * (unsigned)(t + 1);
        unsigned v;
        do {
            asm volatile("ld.acquire.gpu.global.u32 %0, [%1];"
                         : "=r"(v) : "l"(&g_arrive) : "memory");
        } while (v < target);
    }
    __syncthreads();
}

__global__ void __launch_bounds__(TPB_MAIN, 2) k_main() {
    extern __shared__ unsigned s_lut[];                    // NPC * 128 words (34 KB)
    const int lane = threadIdx.x & 31;
    const int w    = threadIdx.x >> 5;                     // warp id in CTA (0..31)
    const int nb   = gridDim.x;
    const int bid  = blockIdx.x;
    const int start = N_INPUT + bid * NPC;                 // first node owned by this CTA
    const unsigned sel16 = (lane & 16) ? 0x3276u : 0x5410u;
    const unsigned sel8  = (lane & 8)  ? 0x3715u : 0x6240u;

    // stage this CTA's LUT slice into shared memory (one-time)
    for (int i = threadIdx.x; i < SLUT_WORDS; i += TPB_MAIN) {
        int node = start + (i >> 7);
        s_lut[i] = (node < N_NODES) ? g_lut[node * LUTW + (i & 127)] : 0u;
    }

    // Pairing: warp w owns pair w; warps 30,31 additionally own pairs 32,33
    // (= w+2). Double duty is OFF the polling warp (0) and staging warps (2,3).
    // Lanes 0..11 hold A's lane-reversed adjacency, lanes 16..27 hold B's.
    const bool laneA = (lane < KMAX);
    const bool laneB = (lane >= 16) && (lane < 16 + KMAX);
    const bool gath  = laneA || laneB;
    const int  niters = (w >= 30) ? 2 : 1;                 // pairs: w, and w+2 for w>=30

    unsigned adjreg[2];
#pragma unroll
    for (int i = 0; i < 2; i++) {
        int p = (i == 0) ? w : (w + 2);
        unsigned ai = DUMMY;
        if (i == 0 || w >= 30) {
            int nA = start + 2 * p, nB = nA + 1;
            if (laneA && nA < N_NODES) ai = (unsigned)g_adj[nA * 16 + lane];
            if (laneB && nB < N_NODES) ai = (unsigned)g_adj[nB * 16 + (lane - 16)];
        }
        adjreg[i] = ai;
    }
    __syncthreads();                                       // s_lut ready

    int cur = 0;
    for (int t = 0; t < TSTEPS; t++) {
        const uint2* __restrict__ S = g_st[cur];
        uint2* __restrict__ D = g_st[cur ^ 1];

        // CTA 0 stages next step's input-layer bits (warps 2,3 — off the
        // polling warp and the double-pair warps)
        if (bid == 0 && threadIdx.x >= 64 && threadIdx.x < 128 && t + 1 < TSTEPS)
            D[threadIdx.x - 64] = g_u[(t + 1) * 64 + (threadIdx.x - 64)];

        // prefetch this warp's gathers before any compute (hide L2 latency)
        uint2 wv[2];
        wv[0] = wv[1] = make_uint2(0u, 0u);
        if (gath) {
            wv[0] = __ldcg(&S[adjreg[0]]);
            if (niters == 2) wv[1] = __ldcg(&S[adjreg[1]]);
        }

#pragma unroll
        for (int i = 0; i < 2; i++) {
            if (i >= niters) break;
            int p  = (i == 0) ? w : (w + 2);
            int nA = start + 2 * p;
            unsigned tl = btrans32(wv[i].x, lane, sel16, sel8);  // [idxA|idxB<<16] b0-31
            unsigned th = btrans32(wv[i].y, lane, sel16, sel8);  // b32-63
            unsigned iAL = tl & 0xfffu, iBL = (tl >> 16) & 0xfffu;
            unsigned iAH = th & 0xfffu, iBH = (th >> 16) & 0xfffu;
            const unsigned* rowA = s_lut + (p << 8);        // local node 2p
            const unsigned* rowB = rowA + LUTW;             // local node 2p+1
            unsigned bAL = lut_bit(rowA, iAL);
            unsigned bAH = lut_bit(rowA, iAH);
            unsigned bBL = lut_bit(rowB, iBL);
            unsigned bBH = lut_bit(rowB, iBH);
            unsigned mAL = __ballot_sync(0xffffffffu, bAL);
            unsigned mAH = __ballot_sync(0xffffffffu, bAH);
            unsigned mBL = __ballot_sync(0xffffffffu, bBL);
            unsigned mBH = __ballot_sync(0xffffffffu, bBH);
            // nA even & N_NODES even -> nA valid implies nB valid; single STG.128.
            if (lane == 0 && nA < N_NODES)
                *(uint4*)&D[nA] = make_uint4(mAL, mAH, mBL, mBH);
        }

        grid_bar(t, nb);
        cur ^= 1;
    }
}

// ---------------- readout: sigmoid(states[:,64:] @ W^T + b) ----------------

__global__ void k_readout(const float* __restrict__ W, const float* __restrict__ bias,
                          float* __restrict__ out) {
    int b   = blockIdx.x;        // 64 blocks
    int tid = threadIdx.x;       // 256 threads
    int lane = tid & 31, wrp = tid >> 5;
    const uint2* __restrict__ S = g_st[0];   // TSTEPS even -> final states in buffer 0

    float acc[N_OUT];
#pragma unroll
    for (int o = 0; o < N_OUT; o++) acc[o] = 0.f;

    const int bsh = b & 31;
    for (int n = N_INPUT + tid; n < N_NODES; n += blockDim.x) {
        uint2 w = S[n];
        unsigned word = (b < 32) ? w.x : w.y;
        float bit = (float)((word >> bsh) & 1u);
        const float* wp = W + (n - N_INPUT);
#pragma unroll
        for (int o = 0; o < N_OUT; o++)
            acc[o] += bit * wp[o * (N_NODES - N_INPUT)];
    }

    __shared__ float part[8][N_OUT];
#pragma unroll
    for (int o = 0; o < N_OUT; o++) {
        float v = acc[o];
#pragma unroll
        for (int off = 16; off; off >>= 1) v += __shfl_down_sync(0xffffffffu, v, off);
        if (lane == 0) part[wrp][o] = v;
    }
    __syncthreads();
    if (tid < N_OUT) {
        float s = bias[tid];
#pragma unroll
        for (int w2 = 0; w2 < 8; w2++) s += part[w2][tid];
        out[b * N_OUT + tid] = 1.0f / (1.0f + expf(-s));
    }
}

// ---------------- launch ----------------

extern "C" void kernel_launch(void* const* d_in, const int* in_sizes, int n_in,
                              void* d_out, int out_size) {
    (void)in_sizes; (void)n_in; (void)out_size;
    const int*   x           = (const int*)d_in[0];
    const int*   w_in        = (const int*)d_in[1];
    const int*   adj_list    = (const int*)d_in[2];
    const int*   adj_mask    = (const int*)d_in[3];
    const int*   lut         = (const int*)d_in[4];
    const int*   init_states = (const int*)d_in[5];
    const float* W_out       = (const float*)d_in[6];
    const float* b_out       = (const float*)d_in[7];
    float* out = (float*)d_out;

    k_pre1<<<1032, 256>>>(x, w_in);                        // pack_x + pack_w
    k_pre2<<<1103, 256>>>(adj_list, adj_mask);             // build_u + pack_adj
    k_pre3<<<80079, 256>>>(lut, init_states);              // pack_lut (vec) + init

    cudaFuncSetAttribute(k_main, cudaFuncAttributeMaxDynamicSharedMemorySize, SLUT_BYTES);
    k_main<<<GRID_MAIN, TPB_MAIN, SLUT_BYTES>>>();         // 4th launch -> ncu capture
    k_readout<<<NBATCH, 256>>>(W_out, b_out, out);
}

// round 15
// speedup vs baseline: 1.4289x; 1.0856x over previous
#include <cuda_runtime.h>
#include <cuda_bf16.h>
#include <cstdint>

#define N_NODES   20000
#define N_INPUT   64
#define KMAX      12
#define NBITS     64
#define N_OUT     10
#define NBATCH    64
#define TSTEPS    128
#define LUTW      128         /* 4096 bits / 32 words */
#define DUMMY     20000
#define ST_SZ     20008
#define TPB_MAIN  1024
#define NPC       68          /* nodes per CTA (even) */
#define PAIRS     (NPC / 2)   /* 34 */
#define GRID_MAIN 294         /* 294*68 = 19992 >= 19936 ; 2 CTAs/SM */
#define SLUT_WORDS (NPC * LUTW)          /* 8704 words */
#define SLUT_BYTES (SLUT_WORDS * 4)      /* 34816 bytes -> 2 CTAs/SM */
#define PRE3_LUTB 20000                  /* lut-pack blocks (4 chunks/warp) */

// LUT bit layout (remapped for vectorized packing):
//   entry e -> word ((e>>7)<<2) | (e&3),  bit (e>>2)&31

// ---------------- device globals (scratch; no allocations allowed) ----------------
__device__ __align__(16) unsigned short g_adj[N_NODES * 16];   // lane-reversed packed adjacency
__device__ __align__(16) unsigned int g_lut[N_NODES * LUTW];   // 10.24 MB bit-packed LUT (remapped layout)
__device__ unsigned char g_non[N_NODES];                       // no-neighbor flag per node
__device__ uint2         g_st[2][ST_SZ];                       // bit-packed states; slot 20000 = always-0 dummy
__device__ uint2         g_u[TSTEPS * 64];                     // input-layer bits u[t][j]
__device__ uint2         g_xb[NBATCH * TSTEPS];                // packed x bits [b][t]
__device__ uint2         g_wc[64];                             // packed w_in columns
__device__ unsigned int  g_arrive;                             // MONOTONIC arrival counter (REDG target)

// ---------------- preprocessing (fused: 3 kernels) ----------------

// pre1: pack_x (blocks 0..1023) + pack_w (blocks 1024..1031)
__global__ void k_pre1(const int* __restrict__ x, const int* __restrict__ w_in) {
    int lane = threadIdx.x & 31;
    if (blockIdx.x < 1024) {
        int wid = (blockIdx.x * 256 + threadIdx.x) >> 5;   // 0..8191
        int b = wid >> 7, t = wid & 127;
        const int* p = x + ((size_t)b * TSTEPS + t) * NBITS;
        unsigned lo = __ballot_sync(0xffffffffu, p[lane] != 0);
        unsigned hi = __ballot_sync(0xffffffffu, p[lane + 32] != 0);
        if (lane == 0) g_xb[b * TSTEPS + t] = make_uint2(lo, hi);
    } else {
        int wid = ((blockIdx.x - 1024) * 256 + threadIdx.x) >> 5;  // 0..63
        unsigned lo = __ballot_sync(0xffffffffu, w_in[lane * 64 + wid] != 0);
        unsigned hi = __ballot_sync(0xffffffffu, w_in[(lane + 32) * 64 + wid] != 0);
        if (lane == 0) g_wc[wid] = make_uint2(lo, hi);
    }
}

// pre2: build_u (blocks 0..1023) + pack_adj (blocks 1024..1102)
__global__ void k_pre2(const int* __restrict__ adj_list, const int* __restrict__ adj_mask) {
    int lane = threadIdx.x & 31;
    if (blockIdx.x < 1024) {
        int wid = (blockIdx.x * 256 + threadIdx.x) >> 5;   // 0..8191
        int t = wid >> 6, j = wid & 63;
        uint2 wc = g_wc[j];
        uint2 xa = g_xb[lane * TSTEPS + t];
        uint2 xb = g_xb[(lane + 32) * TSTEPS + t];
        unsigned lo = __ballot_sync(0xffffffffu, ((xa.x & wc.x) | (xa.y & wc.y)) != 0);
        unsigned hi = __ballot_sync(0xffffffffu, ((xb.x & wc.x) | (xb.y & wc.y)) != 0);
        if (lane == 0) g_u[t * 64 + j] = make_uint2(lo, hi);
    } else {
        int n = (blockIdx.x - 1024) * 256 + threadIdx.x;
        if (n >= N_NODES) return;
        unsigned a[12];
        int any = 0;
#pragma unroll
        for (int k = 0; k < KMAX; k++) {
            int m = adj_mask[n * KMAX + k];
            any |= m;
            a[k] = m ? (unsigned)adj_list[n * KMAX + k] : (unsigned)DUMMY;
        }
        if (!any) {
#pragma unroll
            for (int k = 0; k < KMAX; k++) a[k] = DUMMY;
            a[11] = (unsigned)n;   // idx = old state bit (identity LUT)
        }
        g_non[n] = (unsigned char)(!any);
        unsigned r[16];
#pragma unroll
        for (int l = 0; l < 12; l++) r[l] = a[11 - l];     // lane-reversed
        r[12] = r[13] = r[14] = r[15] = DUMMY;
        uint4 v0, v1;
        v0.x = r[0]  | (r[1]  << 16); v0.y = r[2]  | (r[3]  << 16);
        v0.z = r[4]  | (r[5]  << 16); v0.w = r[6]  | (r[7]  << 16);
        v1.x = r[8]  | (r[9]  << 16); v1.y = r[10] | (r[11] << 16);
        v1.z = r[12] | (r[13] << 16); v1.w = r[14] | (r[15] << 16);
        ((uint4*)g_adj)[n * 2]     = v0;
        ((uint4*)g_adj)[n * 2 + 1] = v1;
    }
}

// pre3: pack_lut, 4 chunks per warp for MLP=4 (blocks 0..19999) +
// state/barrier init (blocks 20000..20078).
__global__ void k_pre3(const int* __restrict__ lut, const int* __restrict__ init_states) {
    if (blockIdx.x < PRE3_LUTB) {
        int gw   = blockIdx.x * 8 + (threadIdx.x >> 5);    // 0..159999
        int lane = threadIdx.x & 31;
        int node = gw >> 3;                                // 8 warps per node
        int c0   = (gw & 7) * 4;                           // chunks c0..c0+3
        uint4 wout[4];
        if (g_non[node]) {
#pragma unroll
            for (int c = 0; c < 4; c++)
                wout[c] = make_uint4(0u, (c0 + c == 0) ? 1u : 0u, 0u, 0u);
        } else {
            const int4* base = (const int4*)(lut + (size_t)node * 4096);
            int4 v0 = __ldcs(&base[(c0 + 0) * 32 + lane]); // 4 independent streaming loads
            int4 v1 = __ldcs(&base[(c0 + 1) * 32 + lane]);
            int4 v2 = __ldcs(&base[(c0 + 2) * 32 + lane]);
            int4 v3 = __ldcs(&base[(c0 + 3) * 32 + lane]);
            wout[0].x = __ballot_sync(0xffffffffu, v0.x != 0);
            wout[0].y = __ballot_sync(0xffffffffu, v0.y != 0);
            wout[0].z = __ballot_sync(0xffffffffu, v0.z != 0);
            wout[0].w = __ballot_sync(0xffffffffu, v0.w != 0);
            wout[1].x = __ballot_sync(0xffffffffu, v1.x != 0);
            wout[1].y = __ballot_sync(0xffffffffu, v1.y != 0);
            wout[1].z = __ballot_sync(0xffffffffu, v1.z != 0);
            wout[1].w = __ballot_sync(0xffffffffu, v1.w != 0);
            wout[2].x = __ballot_sync(0xffffffffu, v2.x != 0);
            wout[2].y = __ballot_sync(0xffffffffu, v2.y != 0);
            wout[2].z = __ballot_sync(0xffffffffu, v2.z != 0);
            wout[2].w = __ballot_sync(0xffffffffu, v2.w != 0);
            wout[3].x = __ballot_sync(0xffffffffu, v3.x != 0);
            wout[3].y = __ballot_sync(0xffffffffu, v3.y != 0);
            wout[3].z = __ballot_sync(0xffffffffu, v3.z != 0);
            wout[3].w = __ballot_sync(0xffffffffu, v3.w != 0);
        }
        if (lane == 0) {
            uint4* outp = ((uint4*)g_lut) + node * (LUTW / 4) + c0;
#pragma unroll
            for (int c = 0; c < 4; c++) outp[c] = wout[c];
        }
    } else {
        int i = (blockIdx.x - PRE3_LUTB) * 256 + threadIdx.x;
        if (i == 0) g_arrive = 0;
        if (i >= ST_SZ) return;
        if (i < N_INPUT) {
            g_st[0][i] = g_u[i];                           // u[0][i]
        } else if (i < N_NODES) {
            int s = init_states[i];
            g_st[0][i] = s ? make_uint2(0xffffffffu, 0xffffffffu) : make_uint2(0u, 0u);
        } else {                                            // dummy + pad: zero both buffers
            g_st[0][i] = make_uint2(0u, 0u);
            g_st[1][i] = make_uint2(0u, 0u);
        }
    }
}

// ---------------- main persistent kernel ----------------

// 32x32 bit-matrix transpose distributed across a warp (5 butterfly stages).
// Stages 16 and 8 are pure byte permutations -> single PRMT each.
__device__ __forceinline__ unsigned btrans32(unsigned x, int lane,
                                             unsigned sel16, unsigned sel8) {
    unsigned y;
    y = __shfl_xor_sync(0xffffffffu, x, 16);
    x = __byte_perm(x, y, sel16);                          // stage 16: PRMT
    y = __shfl_xor_sync(0xffffffffu, x, 8);
    x = __byte_perm(x, y, sel8);                           // stage 8: PRMT
    y = __shfl_xor_sync(0xffffffffu, x, 4);
    x = (lane & 4)  ? ((x & 0xf0f0f0f0u) | ((y & 0xf0f0f0f0u) >> 4))
                    : ((x & 0x0f0f0f0fu) | ((y & 0x0f0f0f0fu) << 4));
    y = __shfl_xor_sync(0xffffffffu, x, 2);
    x = (lane & 2)  ? ((x & 0xccccccccu) | ((y & 0xccccccccu) >> 2))
                    : ((x & 0x33333333u) | ((y & 0x33333333u) << 2));
    y = __shfl_xor_sync(0xffffffffu, x, 1);
    x = (lane & 1)  ? ((x & 0xaaaaaaaau) | ((y & 0xaaaaaaaau) >> 1))
                    : ((x & 0x55555555u) | ((y & 0x55555555u) << 1));
    return x;
}

// remapped-layout LUT lookup: entry idx -> word ((idx>>7)<<2)|(idx&3), bit (idx>>2)&31
__device__ __forceinline__ unsigned lut_bit(const unsigned* __restrict__ row, unsigned idx) {
    unsigned wofs = ((idx >> 5) & ~3u) | (idx & 3u);
    return (row[wofs] >> ((idx >> 2) & 31u)) & 1u;
}

// Validated fence-free barrier (R11/R12): REDG release arrive + acquire spin on
// the single monotonic counter (single hop). No MEMBAR.GL, no CCTL.IVALL.
__device__ __forceinline__ void grid_bar(int t, int nblocks) {
    __syncthreads();
    if (threadIdx.x == 0) {
        asm volatile("red.release.gpu.global.add.u32 [%0], %1;"
                     :: "l"(&g_arrive), "r"(1u) : "memory");
        const unsigned target = (unsigned)nblocks * (unsigned)(t + 1);
        unsigned v;
        do {
            asm volatile("ld.acquire.gpu.global.u32 %0, [%1];"
                         : "=r"(v) : "l"(&g_arrive) : "memory");
        } while (v < target);
    }
    __syncthreads();
}

__global__ void __launch_bounds__(TPB_MAIN, 2) k_main() {
    extern __shared__ unsigned s_lut[];                    // NPC * 128 words (34 KB)
    const int lane = threadIdx.x & 31;
    const int w    = threadIdx.x >> 5;                     // warp id in CTA (0..31)
    const int nb   = gridDim.x;
    const int bid  = blockIdx.x;
    const int start = N_INPUT + bid * NPC;                 // first node owned by this CTA
    const unsigned sel16 = (lane & 16) ? 0x3276u : 0x5410u;
    const unsigned sel8  = (lane & 8)  ? 0x3715u : 0x6240u;

    // stage this CTA's LUT slice into shared memory (one-time)
    for (int i = threadIdx.x; i < SLUT_WORDS; i += TPB_MAIN) {
        int node = start + (i >> 7);
        s_lut[i] = (node < N_NODES) ? g_lut[node * LUTW + (i & 127)] : 0u;
    }

    // Pairing: warp w owns pair w; warps 30,31 additionally own pairs 32,33
    // (= w+2). Double duty stays OFF the polling warp (0) and staging warps (2,3).
    // Lanes 0..11 hold A's lane-reversed adjacency, lanes 16..27 hold B's.
    const bool laneA = (lane < KMAX);
    const bool laneB = (lane >= 16) && (lane < 16 + KMAX);
    const bool gath  = laneA || laneB;
    const bool has2  = (w >= 30);                          // pairs: w, and w+2

    unsigned adjreg[2];
#pragma unroll
    for (int i = 0; i < 2; i++) {
        int p = (i == 0) ? w : (w + 2);
        unsigned ai = DUMMY;
        if (i == 0 || has2) {
            int nA = start + 2 * p, nB = nA + 1;
            if (laneA && nA < N_NODES) ai = (unsigned)g_adj[nA * 16 + lane];
            if (laneB && nB < N_NODES) ai = (unsigned)g_adj[nB * 16 + (lane - 16)];
        }
        adjreg[i] = ai;
    }
    __syncthreads();                                       // s_lut ready

    int cur = 0;
    for (int t = 0; t < TSTEPS; t++) {
        const uint2* __restrict__ S = g_st[cur];
        uint2* __restrict__ D = g_st[cur ^ 1];

        // CTA 0 stages next step's input-layer bits (warps 2,3)
        if (bid == 0 && threadIdx.x >= 64 && threadIdx.x < 128 && t + 1 < TSTEPS)
            D[threadIdx.x - 64] = g_u[(t + 1) * 64 + (threadIdx.x - 64)];

        if (has2) {
            // ---- double-pair path: all 4 transpose chains interleaved ----
            uint2 wv0 = make_uint2(0u, 0u), wv1 = make_uint2(0u, 0u);
            if (gath) {
                wv0 = __ldcg(&S[adjreg[0]]);
                wv1 = __ldcg(&S[adjreg[1]]);
            }
            unsigned tl0 = btrans32(wv0.x, lane, sel16, sel8);
            unsigned th0 = btrans32(wv0.y, lane, sel16, sel8);
            unsigned tl1 = btrans32(wv1.x, lane, sel16, sel8);
            unsigned th1 = btrans32(wv1.y, lane, sel16, sel8);
            const unsigned* rowA0 = s_lut + (w << 8);
            const unsigned* rowB0 = rowA0 + LUTW;
            const unsigned* rowA1 = s_lut + ((w + 2) << 8);
            const unsigned* rowB1 = rowA1 + LUTW;
            unsigned bAL0 = lut_bit(rowA0, tl0 & 0xfffu);
            unsigned bAH0 = lut_bit(rowA0, th0 & 0xfffu);
            unsigned bBL0 = lut_bit(rowB0, (tl0 >> 16) & 0xfffu);
            unsigned bBH0 = lut_bit(rowB0, (th0 >> 16) & 0xfffu);
            unsigned bAL1 = lut_bit(rowA1, tl1 & 0xfffu);
            unsigned bAH1 = lut_bit(rowA1, th1 & 0xfffu);
            unsigned bBL1 = lut_bit(rowB1, (tl1 >> 16) & 0xfffu);
            unsigned bBH1 = lut_bit(rowB1, (th1 >> 16) & 0xfffu);
            unsigned mAL0 = __ballot_sync(0xffffffffu, bAL0);
            unsigned mAH0 = __ballot_sync(0xffffffffu, bAH0);
            unsigned mBL0 = __ballot_sync(0xffffffffu, bBL0);
            unsigned mBH0 = __ballot_sync(0xffffffffu, bBH0);
            unsigned mAL1 = __ballot_sync(0xffffffffu, bAL1);
            unsigned mAH1 = __ballot_sync(0xffffffffu, bAH1);
            unsigned mBL1 = __ballot_sync(0xffffffffu, bBL1);
            unsigned mBH1 = __ballot_sync(0xffffffffu, bBH1);
            int nA0 = start + 2 * w;
            int nA1 = start + 2 * (w + 2);
            if (lane == 0) {
                *(uint4*)&D[nA0] = make_uint4(mAL0, mAH0, mBL0, mBH0);
                if (nA1 < N_NODES)
                    *(uint4*)&D[nA1] = make_uint4(mAL1, mAH1, mBL1, mBH1);
            }
        } else {
            // ---- single-pair path ----
            uint2 wv0 = make_uint2(0u, 0u);
            if (gath) wv0 = __ldcg(&S[adjreg[0]]);
            unsigned tl0 = btrans32(wv0.x, lane, sel16, sel8);
            unsigned th0 = btrans32(wv0.y, lane, sel16, sel8);
            const unsigned* rowA0 = s_lut + (w << 8);
            const unsigned* rowB0 = rowA0 + LUTW;
            unsigned bAL0 = lut_bit(rowA0, tl0 & 0xfffu);
            unsigned bAH0 = lut_bit(rowA0, th0 & 0xfffu);
            unsigned bBL0 = lut_bit(rowB0, (tl0 >> 16) & 0xfffu);
            unsigned bBH0 = lut_bit(rowB0, (th0 >> 16) & 0xfffu);
            unsigned mAL0 = __ballot_sync(0xffffffffu, bAL0);
            unsigned mAH0 = __ballot_sync(0xffffffffu, bAH0);
            unsigned mBL0 = __ballot_sync(0xffffffffu, bBL0);
            unsigned mBH0 = __ballot_sync(0xffffffffu, bBH0);
            int nA0 = start + 2 * w;
            if (lane == 0 && nA0 < N_NODES)
                *(uint4*)&D[nA0] = make_uint4(mAL0, mAH0, mBL0, mBH0);
        }

        grid_bar(t, nb);
        cur ^= 1;
    }
}

// ---------------- readout: sigmoid(states[:,64:] @ W^T + b) ----------------

__global__ void k_readout(const float* __restrict__ W, const float* __restrict__ bias,
                          float* __restrict__ out) {
    int b   = blockIdx.x;        // 64 blocks
    int tid = threadIdx.x;       // 256 threads
    int lane = tid & 31, wrp = tid >> 5;
    const uint2* __restrict__ S = g_st[0];   // TSTEPS even -> final states in buffer 0

    float acc[N_OUT];
#pragma unroll
    for (int o = 0; o < N_OUT; o++) acc[o] = 0.f;

    const int bsh = b & 31;
    for (int n = N_INPUT + tid; n < N_NODES; n += blockDim.x) {
        uint2 w = S[n];
        unsigned word = (b < 32) ? w.x : w.y;
        float bit = (float)((word >> bsh) & 1u);
        const float* wp = W + (n - N_INPUT);
#pragma unroll
        for (int o = 0; o < N_OUT; o++)
            acc[o] += bit * wp[o * (N_NODES - N_INPUT)];
    }

    __shared__ float part[8][N_OUT];
#pragma unroll
    for (int o = 0; o < N_OUT; o++) {
        float v = acc[o];
#pragma unroll
        for (int off = 16; off; off >>= 1) v += __shfl_down_sync(0xffffffffu, v, off);
        if (lane == 0) part[wrp][o] = v;
    }
    __syncthreads();
    if (tid < N_OUT) {
        float s = bias[tid];
#pragma unroll
        for (int w2 = 0; w2 < 8; w2++) s += part[w2][tid];
        out[b * N_OUT + tid] = 1.0f / (1.0f + expf(-s));
    }
}

// ---------------- launch ----------------

extern "C" void kernel_launch(void* const* d_in, const int* in_sizes, int n_in,
                              void* d_out, int out_size) {
    (void)in_sizes; (void)n_in; (void)out_size;
    const int*   x           = (const int*)d_in[0];
    const int*   w_in        = (const int*)d_in[1];
    const int*   adj_list    = (const int*)d_in[2];
    const int*   adj_mask    = (const int*)d_in[3];
    const int*   lut         = (const int*)d_in[4];
    const int*   init_states = (const int*)d_in[5];
    const float* W_out       = (const float*)d_in[6];
    const float* b_out       = (const float*)d_in[7];
    float* out = (float*)d_out;

    k_pre1<<<1032, 256>>>(x, w_in);                        // pack_x + pack_w
    k_pre2<<<1103, 256>>>(adj_list, adj_mask);             // build_u + pack_adj
    k_pre3<<<PRE3_LUTB + 79, 256>>>(lut, init_states);     // pack_lut (MLP=4) + init

    cudaFuncSetAttribute(k_main, cudaFuncAttributeMaxDynamicSharedMemorySize, SLUT_BYTES);
    k_main<<<GRID_MAIN, TPB_MAIN, SLUT_BYTES>>>();         // 4th launch -> ncu capture
    k_readout<<<NBATCH, 256>>>(W_out, b_out, out);
}

// round 16
// speedup vs baseline: 1.6935x; 1.1852x over previous
#include <cuda_runtime.h>
#include <cuda_bf16.h>
#include <cstdint>

#define N_NODES   20000
#define N_INPUT   64
#define KMAX      12
#define NBITS     64
#define N_OUT     10
#define NBATCH    64
#define TSTEPS    128
#define LUTW      128         /* 4096 bits / 32 words */
#define DUMMY     20000
#define ST_SZ     20008
#define TPB_MAIN  1024
#define NPC       68          /* nodes per CTA (even) */
#define PAIRS     (NPC / 2)   /* 34 */
#define GRID_MAIN 294         /* 294*68 = 19992 >= 19936 ; 2 CTAs/SM */
#define SLUT_WORDS (NPC * LUTW)          /* 8704 words */
#define SLUT_BYTES (SLUT_WORDS * 4)      /* 34816 bytes -> 2 CTAs/SM */
#define PRE3_LUTB 20000                  /* lut-pack blocks (4 chunks/warp) */

// LUT bit layout (remapped for vectorized packing):
//   entry e -> word ((e>>7)<<2) | (e&3),  bit (e>>2)&31

// ---------------- device globals (scratch; no allocations allowed) ----------------
__device__ __align__(16) unsigned short g_adj[N_NODES * 16];   // lane-reversed packed adjacency
__device__ __align__(16) unsigned int g_lut[N_NODES * LUTW];   // 10.24 MB bit-packed LUT (remapped layout)
__device__ unsigned char g_non[N_NODES];                       // no-neighbor flag per node
// ROTATING state buffers: g_st[t] is written ONLY during step t-1 (once) and
// read ONLY during step t. No address is ever rewritten -> an SM's L1 can never
// hold a stale copy of a line it reads -> gathers may use default cached loads.
__device__ uint2         g_st[TSTEPS + 1][ST_SZ];              // 20.7 MB; slot 20000.. = always-0 dummy
__device__ uint2         g_u[TSTEPS * 64];                     // input-layer bits u[t][j]
__device__ uint2         g_xb[NBATCH * TSTEPS];                // packed x bits [b][t]
__device__ uint2         g_wc[64];                             // packed w_in columns
__device__ unsigned int  g_arrive;                             // MONOTONIC arrival counter (REDG target)

// ---------------- preprocessing (fused: 3 kernels) ----------------

// pre1: pack_x (blocks 0..1023) + pack_w (blocks 1024..1031)
__global__ void k_pre1(const int* __restrict__ x, const int* __restrict__ w_in) {
    int lane = threadIdx.x & 31;
    if (blockIdx.x < 1024) {
        int wid = (blockIdx.x * 256 + threadIdx.x) >> 5;   // 0..8191
        int b = wid >> 7, t = wid & 127;
        const int* p = x + ((size_t)b * TSTEPS + t) * NBITS;
        unsigned lo = __ballot_sync(0xffffffffu, p[lane] != 0);
        unsigned hi = __ballot_sync(0xffffffffu, p[lane + 32] != 0);
        if (lane == 0) g_xb[b * TSTEPS + t] = make_uint2(lo, hi);
    } else {
        int wid = ((blockIdx.x - 1024) * 256 + threadIdx.x) >> 5;  // 0..63
        unsigned lo = __ballot_sync(0xffffffffu, w_in[lane * 64 + wid] != 0);
        unsigned hi = __ballot_sync(0xffffffffu, w_in[(lane + 32) * 64 + wid] != 0);
        if (lane == 0) g_wc[wid] = make_uint2(lo, hi);
    }
}

// pre2: build_u (blocks 0..1023) + pack_adj (blocks 1024..1102)
__global__ void k_pre2(const int* __restrict__ adj_list, const int* __restrict__ adj_mask) {
    int lane = threadIdx.x & 31;
    if (blockIdx.x < 1024) {
        int wid = (blockIdx.x * 256 + threadIdx.x) >> 5;   // 0..8191
        int t = wid >> 6, j = wid & 63;
        uint2 wc = g_wc[j];
        uint2 xa = g_xb[lane * TSTEPS + t];
        uint2 xb = g_xb[(lane + 32) * TSTEPS + t];
        unsigned lo = __ballot_sync(0xffffffffu, ((xa.x & wc.x) | (xa.y & wc.y)) != 0);
        unsigned hi = __ballot_sync(0xffffffffu, ((xb.x & wc.x) | (xb.y & wc.y)) != 0);
        if (lane == 0) g_u[t * 64 + j] = make_uint2(lo, hi);
    } else {
        int n = (blockIdx.x - 1024) * 256 + threadIdx.x;
        if (n >= N_NODES) return;
        unsigned a[12];
        int any = 0;
#pragma unroll
        for (int k = 0; k < KMAX; k++) {
            int m = adj_mask[n * KMAX + k];
            any |= m;
            a[k] = m ? (unsigned)adj_list[n * KMAX + k] : (unsigned)DUMMY;
        }
        if (!any) {
#pragma unroll
            for (int k = 0; k < KMAX; k++) a[k] = DUMMY;
            a[11] = (unsigned)n;   // idx = old state bit (identity LUT)
        }
        g_non[n] = (unsigned char)(!any);
        unsigned r[16];
#pragma unroll
        for (int l = 0; l < 12; l++) r[l] = a[11 - l];     // lane-reversed
        r[12] = r[13] = r[14] = r[15] = DUMMY;
        uint4 v0, v1;
        v0.x = r[0]  | (r[1]  << 16); v0.y = r[2]  | (r[3]  << 16);
        v0.z = r[4]  | (r[5]  << 16); v0.w = r[6]  | (r[7]  << 16);
        v1.x = r[8]  | (r[9]  << 16); v1.y = r[10] | (r[11] << 16);
        v1.z = r[12] | (r[13] << 16); v1.w = r[14] | (r[15] << 16);
        ((uint4*)g_adj)[n * 2]     = v0;
        ((uint4*)g_adj)[n * 2 + 1] = v1;
    }
}

// pre3: pack_lut, 4 chunks per warp for MLP=4 (blocks 0..19999) +
// state/barrier init (blocks 20000..20078).
__global__ void k_pre3(const int* __restrict__ lut, const int* __restrict__ init_states) {
    if (blockIdx.x < PRE3_LUTB) {
        int gw   = blockIdx.x * 8 + (threadIdx.x >> 5);    // 0..159999
        int lane = threadIdx.x & 31;
        int node = gw >> 3;                                // 8 warps per node
        int c0   = (gw & 7) * 4;                           // chunks c0..c0+3
        uint4 wout[4];
        if (g_non[node]) {
#pragma unroll
            for (int c = 0; c < 4; c++)
                wout[c] = make_uint4(0u, (c0 + c == 0) ? 1u : 0u, 0u, 0u);
        } else {
            const int4* base = (const int4*)(lut + (size_t)node * 4096);
            int4 v0 = __ldcs(&base[(c0 + 0) * 32 + lane]); // 4 independent streaming loads
            int4 v1 = __ldcs(&base[(c0 + 1) * 32 + lane]);
            int4 v2 = __ldcs(&base[(c0 + 2) * 32 + lane]);
            int4 v3 = __ldcs(&base[(c0 + 3) * 32 + lane]);
            wout[0].x = __ballot_sync(0xffffffffu, v0.x != 0);
            wout[0].y = __ballot_sync(0xffffffffu, v0.y != 0);
            wout[0].z = __ballot_sync(0xffffffffu, v0.z != 0);
            wout[0].w = __ballot_sync(0xffffffffu, v0.w != 0);
            wout[1].x = __ballot_sync(0xffffffffu, v1.x != 0);
            wout[1].y = __ballot_sync(0xffffffffu, v1.y != 0);
            wout[1].z = __ballot_sync(0xffffffffu, v1.z != 0);
            wout[1].w = __ballot_sync(0xffffffffu, v1.w != 0);
            wout[2].x = __ballot_sync(0xffffffffu, v2.x != 0);
            wout[2].y = __ballot_sync(0xffffffffu, v2.y != 0);
            wout[2].z = __ballot_sync(0xffffffffu, v2.z != 0);
            wout[2].w = __ballot_sync(0xffffffffu, v2.w != 0);
            wout[3].x = __ballot_sync(0xffffffffu, v3.x != 0);
            wout[3].y = __ballot_sync(0xffffffffu, v3.y != 0);
            wout[3].z = __ballot_sync(0xffffffffu, v3.z != 0);
            wout[3].w = __ballot_sync(0xffffffffu, v3.w != 0);
        }
        if (lane == 0) {
            uint4* outp = ((uint4*)g_lut) + node * (LUTW / 4) + c0;
#pragma unroll
            for (int c = 0; c < 4; c++) outp[c] = wout[c];
        }
    } else {
        int i = (blockIdx.x - PRE3_LUTB) * 256 + threadIdx.x;
        if (i == 0) g_arrive = 0;
        if (i >= ST_SZ) return;
        if (i < N_INPUT) {
            g_st[0][i] = g_u[i];                           // u[0][i]
        } else if (i < N_NODES) {
            int s = init_states[i];
            g_st[0][i] = s ? make_uint2(0xffffffffu, 0xffffffffu) : make_uint2(0u, 0u);
        } else {                                            // dummy+pad: zero in ALL buffers
            for (int b = 0; b <= TSTEPS; b++)
                g_st[b][i] = make_uint2(0u, 0u);
        }
    }
}

// ---------------- main persistent kernel ----------------

// 32x32 bit-matrix transpose distributed across a warp (5 butterfly stages).
// Stages 16 and 8 are pure byte permutations -> single PRMT each.
__device__ __forceinline__ unsigned btrans32(unsigned x, int lane,
                                             unsigned sel16, unsigned sel8) {
    unsigned y;
    y = __shfl_xor_sync(0xffffffffu, x, 16);
    x = __byte_perm(x, y, sel16);                          // stage 16: PRMT
    y = __shfl_xor_sync(0xffffffffu, x, 8);
    x = __byte_perm(x, y, sel8);                           // stage 8: PRMT
    y = __shfl_xor_sync(0xffffffffu, x, 4);
    x = (lane & 4)  ? ((x & 0xf0f0f0f0u) | ((y & 0xf0f0f0f0u) >> 4))
                    : ((x & 0x0f0f0f0fu) | ((y & 0x0f0f0f0fu) << 4));
    y = __shfl_xor_sync(0xffffffffu, x, 2);
    x = (lane & 2)  ? ((x & 0xccccccccu) | ((y & 0xccccccccu) >> 2))
                    : ((x & 0x33333333u) | ((y & 0x33333333u) << 2));
    y = __shfl_xor_sync(0xffffffffu, x, 1);
    x = (lane & 1)  ? ((x & 0xaaaaaaaau) | ((y & 0xaaaaaaaau) >> 1))
                    : ((x & 0x55555555u) | ((y & 0x55555555u) << 1));
    return x;
}

// remapped-layout LUT lookup: entry idx -> word ((idx>>7)<<2)|(idx&3), bit (idx>>2)&31
__device__ __forceinline__ unsigned lut_bit(const unsigned* __restrict__ row, unsigned idx) {
    unsigned wofs = ((idx >> 5) & ~3u) | (idx & 3u);
    return (row[wofs] >> ((idx >> 2) & 31u)) & 1u;
}

// Validated fence-free barrier (R11+): REDG release arrive + acquire spin on
// the single monotonic counter (single hop). No MEMBAR.GL, no CCTL.IVALL.
__device__ __forceinline__ void grid_bar(int t, int nblocks) {
    __syncthreads();
    if (threadIdx.x == 0) {
        asm volatile("red.release.gpu.global.add.u32 [%0], %1;"
                     :: "l"(&g_arrive), "r"(1u) : "memory");
        const unsigned target = (unsigned)nblocks * (unsigned)(t + 1);
        unsigned v;
        do {
            asm volatile("ld.acquire.gpu.global.u32 %0, [%1];"
                         : "=r"(v) : "l"(&g_arrive) : "memory");
        } while (v < target);
    }
    __syncthreads();
}

__global__ void __launch_bounds__(TPB_MAIN, 2) k_main() {
    extern __shared__ unsigned s_lut[];                    // NPC * 128 words (34 KB)
    const int lane = threadIdx.x & 31;
    const int w    = threadIdx.x >> 5;                     // warp id in CTA (0..31)
    const int nb   = gridDim.x;
    const int bid  = blockIdx.x;
    const int start = N_INPUT + bid * NPC;                 // first node owned by this CTA
    const unsigned sel16 = (lane & 16) ? 0x3276u : 0x5410u;
    const unsigned sel8  = (lane & 8)  ? 0x3715u : 0x6240u;

    // stage this CTA's LUT slice into shared memory (one-time)
    for (int i = threadIdx.x; i < SLUT_WORDS; i += TPB_MAIN) {
        int node = start + (i >> 7);
        s_lut[i] = (node < N_NODES) ? g_lut[node * LUTW + (i & 127)] : 0u;
    }

    // Pairing: warp w owns pair w; warps 30,31 additionally own pairs 32,33
    // (= w+2). Double duty stays OFF the polling warp (0) and staging warps (2,3).
    // Lanes 0..11 hold A's lane-reversed adjacency, lanes 16..27 hold B's.
    const bool laneA = (lane < KMAX);
    const bool laneB = (lane >= 16) && (lane < 16 + KMAX);
    const bool gath  = laneA || laneB;
    const bool has2  = (w >= 30);                          // pairs: w, and w+2

    unsigned adjreg[2];
#pragma unroll
    for (int i = 0; i < 2; i++) {
        int p = (i == 0) ? w : (w + 2);
        unsigned ai = DUMMY;
        if (i == 0 || has2) {
            int nA = start + 2 * p, nB = nA + 1;
            if (laneA && nA < N_NODES) ai = (unsigned)g_adj[nA * 16 + lane];
            if (laneB && nB < N_NODES) ai = (unsigned)g_adj[nB * 16 + (lane - 16)];
        }
        adjreg[i] = ai;
    }
    __syncthreads();                                       // s_lut ready

    for (int t = 0; t < TSTEPS; t++) {
        const uint2* __restrict__ S = g_st[t];             // written once, in step t-1
        uint2* __restrict__ D = g_st[t + 1];

        // CTA 0 stages next step's input-layer bits (warps 2,3)
        if (bid == 0 && threadIdx.x >= 64 && threadIdx.x < 128 && t + 1 < TSTEPS)
            D[threadIdx.x - 64] = g_u[(t + 1) * 64 + (threadIdx.x - 64)];

        if (has2) {
            // ---- double-pair path: all 4 transpose chains interleaved ----
            uint2 wv0 = make_uint2(0u, 0u), wv1 = make_uint2(0u, 0u);
            if (gath) {
                wv0 = S[adjreg[0]];                        // default cached load (L1 OK)
                wv1 = S[adjreg[1]];
            }
            unsigned tl0 = btrans32(wv0.x, lane, sel16, sel8);
            unsigned th0 = btrans32(wv0.y, lane, sel16, sel8);
            unsigned tl1 = btrans32(wv1.x, lane, sel16, sel8);
            unsigned th1 = btrans32(wv1.y, lane, sel16, sel8);
            const unsigned* rowA0 = s_lut + (w << 8);
            const unsigned* rowB0 = rowA0 + LUTW;
            const unsigned* rowA1 = s_lut + ((w + 2) << 8);
            const unsigned* rowB1 = rowA1 + LUTW;
            unsigned bAL0 = lut_bit(rowA0, tl0 & 0xfffu);
            unsigned bAH0 = lut_bit(rowA0, th0 & 0xfffu);
            unsigned bBL0 = lut_bit(rowB0, (tl0 >> 16) & 0xfffu);
            unsigned bBH0 = lut_bit(rowB0, (th0 >> 16) & 0xfffu);
            unsigned bAL1 = lut_bit(rowA1, tl1 & 0xfffu);
            unsigned bAH1 = lut_bit(rowA1, th1 & 0xfffu);
            unsigned bBL1 = lut_bit(rowB1, (tl1 >> 16) & 0xfffu);
            unsigned bBH1 = lut_bit(rowB1, (th1 >> 16) & 0xfffu);
            unsigned mAL0 = __ballot_sync(0xffffffffu, bAL0);
            unsigned mAH0 = __ballot_sync(0xffffffffu, bAH0);
            unsigned mBL0 = __ballot_sync(0xffffffffu, bBL0);
            unsigned mBH0 = __ballot_sync(0xffffffffu, bBH0);
            unsigned mAL1 = __ballot_sync(0xffffffffu, bAL1);
            unsigned mAH1 = __ballot_sync(0xffffffffu, bAH1);
            unsigned mBL1 = __ballot_sync(0xffffffffu, bBL1);
            unsigned mBH1 = __ballot_sync(0xffffffffu, bBH1);
            int nA0 = start + 2 * w;
            int nA1 = start + 2 * (w + 2);
            if (lane == 0) {
                *(uint4*)&D[nA0] = make_uint4(mAL0, mAH0, mBL0, mBH0);
                if (nA1 < N_NODES)
                    *(uint4*)&D[nA1] = make_uint4(mAL1, mAH1, mBL1, mBH1);
            }
        } else {
            // ---- single-pair path ----
            uint2 wv0 = make_uint2(0u, 0u);
            if (gath) wv0 = S[adjreg[0]];                  // default cached load (L1 OK)
            unsigned tl0 = btrans32(wv0.x, lane, sel16, sel8);
            unsigned th0 = btrans32(wv0.y, lane, sel16, sel8);
            const unsigned* rowA0 = s_lut + (w << 8);
            const unsigned* rowB0 = rowA0 + LUTW;
            unsigned bAL0 = lut_bit(rowA0, tl0 & 0xfffu);
            unsigned bAH0 = lut_bit(rowA0, th0 & 0xfffu);
            unsigned bBL0 = lut_bit(rowB0, (tl0 >> 16) & 0xfffu);
            unsigned bBH0 = lut_bit(rowB0, (th0 >> 16) & 0xfffu);
            unsigned mAL0 = __ballot_sync(0xffffffffu, bAL0);
            unsigned mAH0 = __ballot_sync(0xffffffffu, bAH0);
            unsigned mBL0 = __ballot_sync(0xffffffffu, bBL0);
            unsigned mBH0 = __ballot_sync(0xffffffffu, bBH0);
            int nA0 = start + 2 * w;
            if (lane == 0 && nA0 < N_NODES)
                *(uint4*)&D[nA0] = make_uint4(mAL0, mAH0, mBL0, mBH0);
        }

        grid_bar(t, nb);
    }
}

// ---------------- readout: sigmoid(states[:,64:] @ W^T + b) ----------------

__global__ void k_readout(const float* __restrict__ W, const float* __restrict__ bias,
                          float* __restrict__ out) {
    int b   = blockIdx.x;        // 64 blocks
    int tid = threadIdx.x;       // 256 threads
    int lane = tid & 31, wrp = tid >> 5;
    const uint2* __restrict__ S = g_st[TSTEPS];   // final states

    float acc[N_OUT];
#pragma unroll
    for (int o = 0; o < N_OUT; o++) acc[o] = 0.f;

    const int bsh = b & 31;
    for (int n = N_INPUT + tid; n < N_NODES; n += blockDim.x) {
        uint2 w = S[n];
        unsigned word = (b < 32) ? w.x : w.y;
        float bit = (float)((word >> bsh) & 1u);
        const float* wp = W + (n - N_INPUT);
#pragma unroll
        for (int o = 0; o < N_OUT; o++)
            acc[o] += bit * wp[o * (N_NODES - N_INPUT)];
    }

    __shared__ float part[8][N_OUT];
#pragma unroll
    for (int o = 0; o < N_OUT; o++) {
        float v = acc[o];
#pragma unroll
        for (int off = 16; off; off >>= 1) v += __shfl_down_sync(0xffffffffu, v, off);
        if (lane == 0) part[wrp][o] = v;
    }
    __syncthreads();
    if (tid < N_OUT) {
        float s = bias[tid];
#pragma unroll
        for (int w2 = 0; w2 < 8; w2++) s += part[w2][tid];
        out[b * N_OUT + tid] = 1.0f / (1.0f + expf(-s));
    }
}

// ---------------- launch ----------------

extern "C" void kernel_launch(void* const* d_in, const int* in_sizes, int n_in,
                              void* d_out, int out_size) {
    (void)in_sizes; (void)n_in; (void)out_size;
    const int*   x           = (const int*)d_in[0];
    const int*   w_in        = (const int*)d_in[1];
    const int*   adj_list    = (const int*)d_in[2];
    const int*   adj_mask    = (const int*)d_in[3];
    const int*   lut         = (const int*)d_in[4];
    const int*   init_states = (const int*)d_in[5];
    const float* W_out       = (const float*)d_in[6];
    const float* b_out       = (const float*)d_in[7];
    float* out = (float*)d_out;

    k_pre1<<<1032, 256>>>(x, w_in);                        // pack_x + pack_w
    k_pre2<<<1103, 256>>>(adj_list, adj_mask);             // build_u + pack_adj
    k_pre3<<<PRE3_LUTB + 79, 256>>>(lut, init_states);     // pack_lut (MLP=4) + init

    cudaFuncSetAttribute(k_main, cudaFuncAttributeMaxDynamicSharedMemorySize, SLUT_BYTES);
    k_main<<<GRID_MAIN, TPB_MAIN, SLUT_BYTES>>>();         // 4th launch -> ncu capture
    k_readout<<<NBATCH, 256>>>(W_out, b_out, out);
}